// round 1
// baseline (speedup 1.0000x reference)
#include <cuda_runtime.h>
#include <cuda_bf16.h>

// Problem constants (fixed by the dataset)
#define NN   50000
#define NFK  256
#define HD   128
#define NL   3

// Scratch: static device arrays (no runtime allocation allowed)
__device__ __align__(16) float g_bufA[NN * HD];   // 25.6 MB
__device__ __align__(16) float g_bufB[NN * HD];   // 25.6 MB
__device__ float g_colsum[(NL + 1) * HD];         // 512 floats

// ---------------------------------------------------------------------------
// GEMM: C[n x 128] = A[n x K] @ W[K x 128] + bias, optional leaky-ReLU,
// fused per-column sum (for the graph-mean readout) via atomics.
// Block: 128 threads, 32 rows x 128 cols per block.
// Thread (tx = t&31, ty = t>>5) computes 8 rows x 4 cols in registers.
// ---------------------------------------------------------------------------
template <int K>
__global__ __launch_bounds__(128)
void gemm_kernel(const float* __restrict__ A, const float* __restrict__ W,
                 const float* __restrict__ bias, float* __restrict__ C,
                 float* __restrict__ colsum_slot, int n, int do_leaky)
{
    __shared__ float sW[32][128];
    __shared__ float sA[32][32];

    const int t   = threadIdx.x;
    const int tx  = t & 31;          // column quad: cols [4*tx, 4*tx+3]
    const int ty  = t >> 5;          // row octet:  rows  [8*ty, 8*ty+7]
    const int row0 = blockIdx.x * 32;

    float acc[8][4];
#pragma unroll
    for (int i = 0; i < 8; i++)
#pragma unroll
        for (int c = 0; c < 4; c++) acc[i][c] = 0.f;

    for (int k0 = 0; k0 < K; k0 += 32) {
        // Stage W chunk: 32 x 128, coalesced
#pragma unroll
        for (int i = 0; i < 32; i++)
            sW[i][t] = W[(k0 + i) * HD + t];
        // Stage A chunk: 32 rows x 32 k
#pragma unroll
        for (int i = 0; i < 8; i++) {
            int idx = t + i * 128;
            int r = idx >> 5, kk = idx & 31;
            int row = row0 + r;
            sA[r][kk] = (row < n) ? A[(size_t)row * K + k0 + kk] : 0.f;
        }
        __syncthreads();

#pragma unroll
        for (int kk = 0; kk < 32; kk++) {
            float4 w = *reinterpret_cast<const float4*>(&sW[kk][tx * 4]);
#pragma unroll
            for (int i = 0; i < 8; i++) {
                float a = sA[ty * 8 + i][kk];   // warp-broadcast
                acc[i][0] = fmaf(a, w.x, acc[i][0]);
                acc[i][1] = fmaf(a, w.y, acc[i][1]);
                acc[i][2] = fmaf(a, w.z, acc[i][2]);
                acc[i][3] = fmaf(a, w.w, acc[i][3]);
            }
        }
        __syncthreads();
    }

    float4 b = *reinterpret_cast<const float4*>(&bias[tx * 4]);
    float cs0 = 0.f, cs1 = 0.f, cs2 = 0.f, cs3 = 0.f;
#pragma unroll
    for (int i = 0; i < 8; i++) {
        int row = row0 + ty * 8 + i;
        if (row < n) {
            float4 v;
            v.x = acc[i][0] + b.x;
            v.y = acc[i][1] + b.y;
            v.z = acc[i][2] + b.z;
            v.w = acc[i][3] + b.w;
            if (do_leaky) {
                v.x = v.x > 0.f ? v.x : 0.01f * v.x;
                v.y = v.y > 0.f ? v.y : 0.01f * v.y;
                v.z = v.z > 0.f ? v.z : 0.01f * v.z;
                v.w = v.w > 0.f ? v.w : 0.01f * v.w;
            }
            *reinterpret_cast<float4*>(&C[(size_t)row * HD + tx * 4]) = v;
            cs0 += v.x; cs1 += v.y; cs2 += v.z; cs3 += v.w;
        }
    }
    atomicAdd(&colsum_slot[tx * 4 + 0], cs0);
    atomicAdd(&colsum_slot[tx * 4 + 1], cs1);
    atomicAdd(&colsum_slot[tx * 4 + 2], cs2);
    atomicAdd(&colsum_slot[tx * 4 + 3], cs3);
}

// ---------------------------------------------------------------------------
// Scatter-add: agg[dst] += h[src] * (scaled ? 1/deg[src] : 1)
// One warp per edge; each lane moves one float4 (128 floats = 32 float4).
// Uses sm_90+ vectorized float4 atomicAdd.
// ---------------------------------------------------------------------------
__global__ __launch_bounds__(256)
void scatter_kernel(const float* __restrict__ h, float* __restrict__ agg,
                    const int* __restrict__ src, const int* __restrict__ dst,
                    const float* __restrict__ degree, int e, int scaled)
{
    int warp = (blockIdx.x * blockDim.x + threadIdx.x) >> 5;
    int lane = threadIdx.x & 31;
    if (warp >= e) return;
    int s = src[warp];
    int d = dst[warp];

    float4 v = *reinterpret_cast<const float4*>(h + (size_t)s * HD + lane * 4);
    if (scaled) {
        float inv = 1.0f / degree[s];
        v.x *= inv; v.y *= inv; v.z *= inv; v.w *= inv;
    }
    atomicAdd(reinterpret_cast<float4*>(agg + (size_t)d * HD + lane * 4), v);
}

// ---------------------------------------------------------------------------
// Readout: g = (colsum/N) @ Wpred + bpred ; logits = g @ Wcls + bcls ; softmax
// ---------------------------------------------------------------------------
__global__ void final_kernel(const float* __restrict__ colsum,
                             const float* __restrict__ Wpred, const float* __restrict__ bpred,
                             const float* __restrict__ Wcls,  const float* __restrict__ bcls,
                             float* __restrict__ out, float invn)
{
    __shared__ float g[HD];
    int t = threadIdx.x;   // 128 threads, one per hidden unit
    float acc = bpred[t];
    for (int k = 0; k < (NL + 1) * HD; k++)
        acc = fmaf(colsum[k] * invn, Wpred[k * HD + t], acc);
    g[t] = acc;
    __syncthreads();
    if (t == 0) {
        float l0 = bcls[0], l1 = bcls[1];
        for (int j = 0; j < HD; j++) {
            l0 = fmaf(g[j], Wcls[j * 2 + 0], l0);
            l1 = fmaf(g[j], Wcls[j * 2 + 1], l1);
        }
        float m  = fmaxf(l0, l1);
        float e0 = expf(l0 - m), e1 = expf(l1 - m);
        float inv = 1.0f / (e0 + e1);
        out[0] = e0 * inv;
        out[1] = e1 * inv;
    }
}

// ---------------------------------------------------------------------------
extern "C" void kernel_launch(void* const* d_in, const int* in_sizes, int n_in,
                              void* d_out, int out_size)
{
    const float* node_feat = (const float*)d_in[0];
    // d_in[1] edge_feat, d_in[2] base_data: unused by the reference graph
    const float* degree    = (const float*)d_in[3];
    const float* Wn        = (const float*)d_in[4];
    const float* bn        = (const float*)d_in[5];
    // d_in[6] We, d_in[7] be: edge projection is dead code
    const float* Wgcn      = (const float*)d_in[8];
    const float* bgcn      = (const float*)d_in[9];
    const float* Wpred     = (const float*)d_in[10];
    const float* bpred     = (const float*)d_in[11];
    const float* Wcls      = (const float*)d_in[12];
    const float* bcls      = (const float*)d_in[13];
    const int*   src       = (const int*)d_in[14];
    const int*   dst       = (const int*)d_in[15];

    const int n = in_sizes[3];    // degree has N elements
    const int e = in_sizes[14];   // src has E elements

    float *A, *B, *CS;
    cudaGetSymbolAddress((void**)&A,  g_bufA);
    cudaGetSymbolAddress((void**)&B,  g_bufB);
    cudaGetSymbolAddress((void**)&CS, g_colsum);

    const int gemm_blocks    = (n + 31) / 32;
    const int scatter_blocks = (e + 7) / 8;     // 8 warps (edges) per 256-thread block

    // zero the column-sum accumulator every replay
    cudaMemsetAsync(CS, 0, (NL + 1) * HD * sizeof(float));

    // h0 = node_feat @ Wn + bn ; colsum slot 0
    gemm_kernel<NFK><<<gemm_blocks, 128>>>(node_feat, Wn, bn, A, CS, n, 0);

    // fusion: h = segment_sum(h0[src], dst)
    cudaMemsetAsync(B, 0, (size_t)n * HD * sizeof(float));
    scatter_kernel<<<scatter_blocks, 256>>>(A, B, src, dst, degree, e, 0);

    // 3 GCN layers: h lives in B, scratch in A
    for (int l = 0; l < NL; l++) {
        // agg = h (self term) then scatter-add of h[src]/deg[src]
        cudaMemcpyAsync(A, B, (size_t)n * HD * sizeof(float), cudaMemcpyDeviceToDevice);
        scatter_kernel<<<scatter_blocks, 256>>>(B, A, src, dst, degree, e, 1);
        // h = leaky_relu(agg @ Wgcn + bgcn) ; colsum slot l+1
        gemm_kernel<HD><<<gemm_blocks, 128>>>(A, Wgcn, bgcn, B, CS + (l + 1) * HD, n, 1);
    }

    final_kernel<<<1, HD>>>(CS, Wpred, bpred, Wcls, bcls, (float*)d_out, 1.0f / (float)n);
}

// round 3
// speedup vs baseline: 1.4833x; 1.4833x over previous
#include <cuda_runtime.h>
#include <cuda_bf16.h>

// Problem constants (fixed by the dataset)
#define NN   50000
#define NFK  256
#define HD   128
#define NL   3

// Scratch: static device arrays (no runtime allocation allowed)
__device__ __align__(16) float g_bufA[NN * HD];   // 25.6 MB
__device__ __align__(16) float g_bufB[NN * HD];   // 25.6 MB
__device__ float g_colsum[(NL + 1) * HD];         // 512 floats

// Packed fp32x2 FMA (Blackwell): d = a*b + d elementwise on 2 packed floats.
__device__ __forceinline__ void ffma2(unsigned long long& d,
                                      unsigned long long a,
                                      unsigned long long b)
{
    asm("fma.rn.f32x2 %0, %1, %2, %3;" : "=l"(d) : "l"(a), "l"(b), "l"(d));
}

// ---------------------------------------------------------------------------
// GEMM: C[n x 128] = A[n x K] @ W[K x 128] + bias, optional leaky-ReLU,
// fused per-column sum (graph-mean readout) and optional dual-write (aux).
// Tile: 128 rows x 128 cols, 256 threads, each thread 8 rows x 8 cols.
// Inner product uses packed f32x2 FMA: 32 FFMA2 per k-step per thread.
// 'a' operands are stored duplicated (float2{a,a}) so LDS.64 gives the
// packed broadcast directly.
// ---------------------------------------------------------------------------
template <int K>
__global__ __launch_bounds__(256, 2)
void gemm_kernel(const float* __restrict__ A, const float* __restrict__ W,
                 const float* __restrict__ bias, float* __restrict__ C,
                 float* __restrict__ aux, float* __restrict__ colsum_slot,
                 int n, int do_leaky)
{
    __shared__ float  sW[16 * 128];        // 8 KB  (also reused for colsum reduce)
    __shared__ float2 sA[128 * 17];        // 17.4 KB, row stride 17 pairs (34 floats)

    const int t    = threadIdx.x;
    const int tx   = t & 15;               // col octet: cols [8*tx, 8*tx+7]
    const int ty   = t >> 4;               // row octet: rows [8*ty, 8*ty+7]
    const int row0 = blockIdx.x * 128;

    unsigned long long acc[8][4];
#pragma unroll
    for (int i = 0; i < 8; i++)
#pragma unroll
        for (int j = 0; j < 4; j++) acc[i][j] = 0ull;

    for (int k0 = 0; k0 < K; k0 += 16) {
        // ---- stage W chunk: 16 x 128 floats, coalesced (512 float4) ----
        {
            const float4* Wv = reinterpret_cast<const float4*>(W + (size_t)k0 * HD);
            reinterpret_cast<float4*>(sW)[t]       = Wv[t];
            reinterpret_cast<float4*>(sW)[t + 256] = Wv[t + 256];
        }
        // ---- stage A chunk: 128 rows x 16 k, duplicated pairs ----
#pragma unroll
        for (int j = 0; j < 2; j++) {
            int f   = t + j * 256;         // 0..511 float4 slots
            int r   = f >> 2;              // local row 0..127
            int kv  = (f & 3) * 4;         // k offset within chunk
            int row = row0 + r;
            float4 v = make_float4(0.f, 0.f, 0.f, 0.f);
            if (row < n)
                v = *reinterpret_cast<const float4*>(A + (size_t)row * K + k0 + kv);
            float2* dp = &sA[r * 17 + 0];
            dp[kv + 0] = make_float2(v.x, v.x);
            dp[kv + 1] = make_float2(v.y, v.y);
            dp[kv + 2] = make_float2(v.z, v.z);
            dp[kv + 3] = make_float2(v.w, v.w);
        }
        __syncthreads();

#pragma unroll
        for (int kk = 0; kk < 16; kk++) {
            unsigned long long wv[4];
#pragma unroll
            for (int j = 0; j < 4; j++)
                wv[j] = *reinterpret_cast<const unsigned long long*>(
                            &sW[kk * 128 + tx * 8 + 2 * j]);
#pragma unroll
            for (int i = 0; i < 8; i++) {
                unsigned long long av = *reinterpret_cast<const unsigned long long*>(
                                            &sA[(ty * 8 + i) * 17 + kk]);
#pragma unroll
                for (int j = 0; j < 4; j++) ffma2(acc[i][j], av, wv[j]);
            }
        }
        __syncthreads();
    }

    // ---- epilogue: bias, activation, store (C and optional aux), colsum ----
    float2 b[4];
#pragma unroll
    for (int j = 0; j < 4; j++)
        b[j] = *reinterpret_cast<const float2*>(&bias[tx * 8 + 2 * j]);

    float cs[8];
#pragma unroll
    for (int c = 0; c < 8; c++) cs[c] = 0.f;

#pragma unroll
    for (int i = 0; i < 8; i++) {
        int row = row0 + ty * 8 + i;
        if (row < n) {
            float2 v[4];
#pragma unroll
            for (int j = 0; j < 4; j++) {
                float2 a2 = *reinterpret_cast<float2*>(&acc[i][j]);
                v[j].x = a2.x + b[j].x;
                v[j].y = a2.y + b[j].y;
                if (do_leaky) {
                    v[j].x = v[j].x > 0.f ? v[j].x : 0.01f * v[j].x;
                    v[j].y = v[j].y > 0.f ? v[j].y : 0.01f * v[j].y;
                }
                cs[2 * j]     += v[j].x;
                cs[2 * j + 1] += v[j].y;
            }
            float4 o0 = make_float4(v[0].x, v[0].y, v[1].x, v[1].y);
            float4 o1 = make_float4(v[2].x, v[2].y, v[3].x, v[3].y);
            size_t base = (size_t)row * HD + tx * 8;
            *reinterpret_cast<float4*>(C + base)     = o0;
            *reinterpret_cast<float4*>(C + base + 4) = o1;
            if (aux) {
                *reinterpret_cast<float4*>(aux + base)     = o0;
                *reinterpret_cast<float4*>(aux + base + 4) = o1;
            }
        }
    }

    // block-level colsum reduction in smem (reuse sW as [16][128])
    __syncthreads();
#pragma unroll
    for (int c = 0; c < 8; c++) sW[ty * 128 + tx * 8 + c] = cs[c];
    __syncthreads();
    if (t < 128) {
        float s = 0.f;
#pragma unroll
        for (int r = 0; r < 16; r++) s += sW[r * 128 + t];
        atomicAdd(&colsum_slot[t], s);
    }
}

// ---------------------------------------------------------------------------
// Scatter-add: agg[dst] += h[src] * (scaled ? 1/deg[src] : 1)
// One warp per edge; each lane moves one float4 via vectorized atomicAdd.
// ---------------------------------------------------------------------------
__global__ __launch_bounds__(256)
void scatter_kernel(const float* __restrict__ h, float* __restrict__ agg,
                    const int* __restrict__ src, const int* __restrict__ dst,
                    const float* __restrict__ degree, int e, int scaled)
{
    int warp = (blockIdx.x * blockDim.x + threadIdx.x) >> 5;
    int lane = threadIdx.x & 31;
    if (warp >= e) return;
    int s = src[warp];
    int d = dst[warp];

    float4 v = *reinterpret_cast<const float4*>(h + (size_t)s * HD + lane * 4);
    if (scaled) {
        float inv = 1.0f / degree[s];
        v.x *= inv; v.y *= inv; v.z *= inv; v.w *= inv;
    }
    atomicAdd(reinterpret_cast<float4*>(agg + (size_t)d * HD + lane * 4), v);
}

// ---------------------------------------------------------------------------
// Readout: g = (colsum/N) @ Wpred + bpred ; logits = g @ Wcls + bcls ; softmax
// ---------------------------------------------------------------------------
__global__ void final_kernel(const float* __restrict__ colsum,
                             const float* __restrict__ Wpred, const float* __restrict__ bpred,
                             const float* __restrict__ Wcls,  const float* __restrict__ bcls,
                             float* __restrict__ out, float invn)
{
    __shared__ float g[HD];
    int t = threadIdx.x;   // 128 threads, one per hidden unit
    float acc = bpred[t];
    for (int k = 0; k < (NL + 1) * HD; k++)
        acc = fmaf(colsum[k] * invn, Wpred[k * HD + t], acc);
    g[t] = acc;
    __syncthreads();
    if (t == 0) {
        float l0 = bcls[0], l1 = bcls[1];
        for (int j = 0; j < HD; j++) {
            l0 = fmaf(g[j], Wcls[j * 2 + 0], l0);
            l1 = fmaf(g[j], Wcls[j * 2 + 1], l1);
        }
        float m  = fmaxf(l0, l1);
        float e0 = expf(l0 - m), e1 = expf(l1 - m);
        float inv = 1.0f / (e0 + e1);
        out[0] = e0 * inv;
        out[1] = e1 * inv;
    }
}

// ---------------------------------------------------------------------------
extern "C" void kernel_launch(void* const* d_in, const int* in_sizes, int n_in,
                              void* d_out, int out_size)
{
    const float* node_feat = (const float*)d_in[0];
    // d_in[1] edge_feat, d_in[2] base_data: unused by the reference graph
    const float* degree    = (const float*)d_in[3];
    const float* Wn        = (const float*)d_in[4];
    const float* bn        = (const float*)d_in[5];
    // d_in[6] We, d_in[7] be: edge projection is dead code
    const float* Wgcn      = (const float*)d_in[8];
    const float* bgcn      = (const float*)d_in[9];
    const float* Wpred     = (const float*)d_in[10];
    const float* bpred     = (const float*)d_in[11];
    const float* Wcls      = (const float*)d_in[12];
    const float* bcls      = (const float*)d_in[13];
    const int*   src       = (const int*)d_in[14];
    const int*   dst       = (const int*)d_in[15];

    const int n = in_sizes[3];    // degree has N elements
    const int e = in_sizes[14];   // src has E elements

    float *A, *B, *CS;
    cudaGetSymbolAddress((void**)&A,  g_bufA);
    cudaGetSymbolAddress((void**)&B,  g_bufB);
    cudaGetSymbolAddress((void**)&CS, g_colsum);

    const int gemm_blocks    = (n + 127) / 128;
    const int scatter_blocks = (e + 7) / 8;     // 8 warps (edges) per 256-thread block

    // zero the column-sum accumulator every replay
    cudaMemsetAsync(CS, 0, (NL + 1) * HD * sizeof(float));

    // h0 = node_feat @ Wn + bn -> A ; colsum slot 0
    gemm_kernel<NFK><<<gemm_blocks, 256>>>(node_feat, Wn, bn, A, nullptr, CS, n, 0);

    // fusion: B = segment_sum(h0[src], dst)
    cudaMemsetAsync(B, 0, (size_t)n * HD * sizeof(float));
    scatter_kernel<<<scatter_blocks, 256>>>(A, B, src, dst, degree, e, 0);

    // layer 0: self-term init A = B (only memcpy left), scatter, gemm (dual-writes
    // its output into A as the self-term init for layer 1)
    cudaMemcpyAsync(A, B, (size_t)n * HD * sizeof(float), cudaMemcpyDeviceToDevice);
    scatter_kernel<<<scatter_blocks, 256>>>(B, A, src, dst, degree, e, 1);
    gemm_kernel<HD><<<gemm_blocks, 256>>>(A, Wgcn, bgcn, B, A, CS + 1 * HD, n, 1);

    // layer 1: A already = h1
    scatter_kernel<<<scatter_blocks, 256>>>(B, A, src, dst, degree, e, 1);
    gemm_kernel<HD><<<gemm_blocks, 256>>>(A, Wgcn, bgcn, B, A, CS + 2 * HD, n, 1);

    // layer 2: A already = h2; no aux needed
    scatter_kernel<<<scatter_blocks, 256>>>(B, A, src, dst, degree, e, 1);
    gemm_kernel<HD><<<gemm_blocks, 256>>>(A, Wgcn, bgcn, B, nullptr, CS + 3 * HD, n, 1);

    final_kernel<<<1, HD>>>(CS, Wpred, bpred, Wcls, bcls, (float*)d_out, 1.0f / (float)n);
}

// round 4
// speedup vs baseline: 1.9467x; 1.3124x over previous
#include <cuda_runtime.h>
#include <cuda_bf16.h>

// Problem constants (fixed by the dataset)
#define NN   50000
#define EE   800000
#define NFK  256
#define HD   128
#define NL   3

typedef unsigned long long ull;

// Scratch: static device arrays (no runtime allocation allowed)
__device__ __align__(16) float g_bufA[NN * HD];     // 25.6 MB
__device__ __align__(16) float g_bufB[NN * HD];     // 25.6 MB
__device__ float g_colsum[(NL + 1) * HD];           // 512 floats
// CSR scratch
__device__ int   g_cnt[NN];
__device__ int   g_rowptr[NN + 1];
__device__ int   g_offs[NN];
__device__ int   g_esrc[EE];
__device__ float g_rscale[EE];

// Packed fp32x2 FMA (Blackwell): d = a*b + d elementwise on 2 packed floats.
__device__ __forceinline__ void ffma2(ull& d, ull a, ull b)
{
    asm("fma.rn.f32x2 %0, %1, %2, %3;" : "=l"(d) : "l"(a), "l"(b), "l"(d));
}

// cp.async 16B global->shared
__device__ __forceinline__ void cp16(void* smem, const void* g)
{
    unsigned sa = (unsigned)__cvta_generic_to_shared(smem);
    asm volatile("cp.async.cg.shared.global [%0], [%1], 16;" :: "r"(sa), "l"(g));
}
__device__ __forceinline__ void cp_commit() { asm volatile("cp.async.commit_group;"); }
__device__ __forceinline__ void cp_wait0()  { asm volatile("cp.async.wait_group 0;" ::: "memory"); }

// ---------------------------------------------------------------------------
// CSR build (per replay; order within a dst bucket is arbitrary -> fp sum
// order differs from reference only within tolerance)
// ---------------------------------------------------------------------------
__global__ void hist_kernel(const int* __restrict__ dst, int e)
{
    int i = blockIdx.x * blockDim.x + threadIdx.x;
    if (i < e) atomicAdd(&g_cnt[dst[i]], 1);
}

__global__ __launch_bounds__(1024)
void scan_kernel(int n)
{
    __shared__ int part[1024];
    int t = threadIdx.x;
    int chunk = (n + 1023) >> 10;
    int beg = t * chunk, end = min(beg + chunk, n);
    int s = 0;
    for (int i = beg; i < end; i++) s += g_cnt[i];
    part[t] = s;
    __syncthreads();
    for (int off = 1; off < 1024; off <<= 1) {
        int v = (t >= off) ? part[t - off] : 0;
        __syncthreads();
        part[t] += v;
        __syncthreads();
    }
    int run = part[t] - s;   // exclusive prefix of this thread's chunk
    for (int i = beg; i < end; i++) {
        g_rowptr[i] = run;
        g_offs[i]   = run;
        run += g_cnt[i];
    }
    if (end == n) g_rowptr[n] = run;   // all such threads write the same total
}

__global__ void fill_kernel(const int* __restrict__ src, const int* __restrict__ dst,
                            const float* __restrict__ degree, int e)
{
    int i = blockIdx.x * blockDim.x + threadIdx.x;
    if (i >= e) return;
    int s = src[i], d = dst[i];
    int pos = atomicAdd(&g_offs[d], 1);
    g_esrc[pos]   = s;
    g_rscale[pos] = 1.0f / degree[s];
}

// ---------------------------------------------------------------------------
// Gather: out[v] = (MODE ? h[v] : 0) + sum_{u->v} h[u] * (MODE ? 1/deg[u] : 1)
// One warp per node, lane = float4 column chunk. Unrolled x4 for MLP.
// ---------------------------------------------------------------------------
template <int MODE>
__global__ __launch_bounds__(256)
void gather_kernel(const float4* __restrict__ h, float4* __restrict__ out, int n)
{
    int w    = (blockIdx.x * blockDim.x + threadIdx.x) >> 5;
    int lane = threadIdx.x & 31;
    if (w >= n) return;
    int beg = g_rowptr[w], end = g_rowptr[w + 1];

    float4 acc;
    if (MODE) acc = h[(size_t)w * 32 + lane];
    else      acc = make_float4(0.f, 0.f, 0.f, 0.f);

    int i = beg;
    for (; i + 4 <= end; i += 4) {
        int s0 = g_esrc[i], s1 = g_esrc[i + 1], s2 = g_esrc[i + 2], s3 = g_esrc[i + 3];
        float4 x0 = h[(size_t)s0 * 32 + lane];
        float4 x1 = h[(size_t)s1 * 32 + lane];
        float4 x2 = h[(size_t)s2 * 32 + lane];
        float4 x3 = h[(size_t)s3 * 32 + lane];
        float c0 = 1.f, c1 = 1.f, c2 = 1.f, c3 = 1.f;
        if (MODE) { c0 = g_rscale[i]; c1 = g_rscale[i + 1]; c2 = g_rscale[i + 2]; c3 = g_rscale[i + 3]; }
        acc.x = fmaf(x0.x, c0, acc.x); acc.y = fmaf(x0.y, c0, acc.y);
        acc.z = fmaf(x0.z, c0, acc.z); acc.w = fmaf(x0.w, c0, acc.w);
        acc.x = fmaf(x1.x, c1, acc.x); acc.y = fmaf(x1.y, c1, acc.y);
        acc.z = fmaf(x1.z, c1, acc.z); acc.w = fmaf(x1.w, c1, acc.w);
        acc.x = fmaf(x2.x, c2, acc.x); acc.y = fmaf(x2.y, c2, acc.y);
        acc.z = fmaf(x2.z, c2, acc.z); acc.w = fmaf(x2.w, c2, acc.w);
        acc.x = fmaf(x3.x, c3, acc.x); acc.y = fmaf(x3.y, c3, acc.y);
        acc.z = fmaf(x3.z, c3, acc.z); acc.w = fmaf(x3.w, c3, acc.w);
    }
    for (; i < end; i++) {
        int s = g_esrc[i];
        float4 x = h[(size_t)s * 32 + lane];
        float c = MODE ? g_rscale[i] : 1.f;
        acc.x = fmaf(x.x, c, acc.x); acc.y = fmaf(x.y, c, acc.y);
        acc.z = fmaf(x.z, c, acc.z); acc.w = fmaf(x.w, c, acc.w);
    }
    out[(size_t)w * 32 + lane] = acc;
}

// ---------------------------------------------------------------------------
// GEMM: C[n x 128] = A[n x K] @ W[K x 128] + bias, optional leaky-ReLU,
// fused per-column sum. Tile 128x128, 256 threads, 8x8 outputs/thread via
// packed f32x2 FMA. Double-buffered staging: W via cp.async, A via register
// prefetch; ONE __syncthreads per 16-k chunk.
// Dynamic smem layout: sW[2][16*128] floats, sA[2][128*17] float2.
// ---------------------------------------------------------------------------
#define GEMM_SMEM (2 * 16 * 128 * 4 + 2 * 128 * 17 * 8)   // 51200 bytes

template <int K>
__global__ __launch_bounds__(256, 2)
void gemm_kernel(const float* __restrict__ A, const float* __restrict__ W,
                 const float* __restrict__ bias, float* __restrict__ C,
                 float* __restrict__ colsum_slot, int n, int do_leaky)
{
    extern __shared__ float smem_dyn[];
    float*  sW = smem_dyn;                           // 2 x 2048 floats
    float2* sA = (float2*)(smem_dyn + 2 * 16 * 128); // 2 x 2176 float2

    const int t    = threadIdx.x;
    const int tx   = t & 15;               // col octet: cols [8*tx, 8*tx+7]
    const int ty   = t >> 4;               // row octet: rows [8*ty, 8*ty+7]
    const int row0 = blockIdx.x * 128;
    constexpr int NC = K / 16;

    // A staging geometry (fixed per thread)
    const int f0 = t,        r0 = f0 >> 2, kv0 = (f0 & 3) * 4;
    const int f1 = t + 256,  r1 = f1 >> 2, kv1 = (f1 & 3) * 4;
    const int grow0 = row0 + r0, grow1 = row0 + r1;

    ull acc[8][4];
#pragma unroll
    for (int i = 0; i < 8; i++)
#pragma unroll
        for (int j = 0; j < 4; j++) acc[i][j] = 0ull;

    // ---- prologue: stage chunk 0 ----
    {
        const float4* Wv = reinterpret_cast<const float4*>(W);
        cp16(&reinterpret_cast<float4*>(sW)[t], Wv + t);
        cp16(&reinterpret_cast<float4*>(sW)[t + 256], Wv + t + 256);
        cp_commit();
        float4 v0 = make_float4(0, 0, 0, 0), v1 = make_float4(0, 0, 0, 0);
        if (grow0 < n) v0 = *reinterpret_cast<const float4*>(A + (size_t)grow0 * K + kv0);
        if (grow1 < n) v1 = *reinterpret_cast<const float4*>(A + (size_t)grow1 * K + kv1);
        float2* dp0 = &sA[r0 * 17];
        dp0[kv0 + 0] = make_float2(v0.x, v0.x); dp0[kv0 + 1] = make_float2(v0.y, v0.y);
        dp0[kv0 + 2] = make_float2(v0.z, v0.z); dp0[kv0 + 3] = make_float2(v0.w, v0.w);
        float2* dp1 = &sA[r1 * 17];
        dp1[kv1 + 0] = make_float2(v1.x, v1.x); dp1[kv1 + 1] = make_float2(v1.y, v1.y);
        dp1[kv1 + 2] = make_float2(v1.z, v1.z); dp1[kv1 + 3] = make_float2(v1.w, v1.w);
        cp_wait0();
        __syncthreads();
    }

    for (int c = 0; c < NC; c++) {
        const int cur = c & 1, nxt = cur ^ 1;
        float4 v0, v1;
        const bool pre = (c + 1 < NC);
        if (pre) {
            const int k0n = (c + 1) * 16;
            const float4* Wv = reinterpret_cast<const float4*>(W + (size_t)k0n * HD);
            float4* sWn = reinterpret_cast<float4*>(sW + nxt * 2048);
            cp16(&sWn[t], Wv + t);
            cp16(&sWn[t + 256], Wv + t + 256);
            cp_commit();
            v0 = make_float4(0, 0, 0, 0); v1 = make_float4(0, 0, 0, 0);
            if (grow0 < n) v0 = *reinterpret_cast<const float4*>(A + (size_t)grow0 * K + k0n + kv0);
            if (grow1 < n) v1 = *reinterpret_cast<const float4*>(A + (size_t)grow1 * K + k0n + kv1);
        }

        // ---- compute chunk 'cur' ----
        const float*  sWc = sW + cur * 2048;
        const float2* sAc = sA + cur * 2176;
#pragma unroll
        for (int kk = 0; kk < 16; kk++) {
            ull wv[4];
#pragma unroll
            for (int j = 0; j < 4; j++)
                wv[j] = *reinterpret_cast<const ull*>(&sWc[kk * 128 + tx * 8 + 2 * j]);
#pragma unroll
            for (int i = 0; i < 8; i++) {
                ull av = *reinterpret_cast<const ull*>(&sAc[(ty * 8 + i) * 17 + kk]);
#pragma unroll
                for (int j = 0; j < 4; j++) ffma2(acc[i][j], av, wv[j]);
            }
        }

        if (pre) {
            float2* dp0 = &sA[nxt * 2176 + r0 * 17];
            dp0[kv0 + 0] = make_float2(v0.x, v0.x); dp0[kv0 + 1] = make_float2(v0.y, v0.y);
            dp0[kv0 + 2] = make_float2(v0.z, v0.z); dp0[kv0 + 3] = make_float2(v0.w, v0.w);
            float2* dp1 = &sA[nxt * 2176 + r1 * 17];
            dp1[kv1 + 0] = make_float2(v1.x, v1.x); dp1[kv1 + 1] = make_float2(v1.y, v1.y);
            dp1[kv1 + 2] = make_float2(v1.z, v1.z); dp1[kv1 + 3] = make_float2(v1.w, v1.w);
            cp_wait0();
            __syncthreads();
        }
    }

    // ---- epilogue: bias, activation, store, colsum ----
    float2 b[4];
#pragma unroll
    for (int j = 0; j < 4; j++)
        b[j] = *reinterpret_cast<const float2*>(&bias[tx * 8 + 2 * j]);

    float cs[8];
#pragma unroll
    for (int c = 0; c < 8; c++) cs[c] = 0.f;

#pragma unroll
    for (int i = 0; i < 8; i++) {
        int row = row0 + ty * 8 + i;
        if (row < n) {
            float2 v[4];
#pragma unroll
            for (int j = 0; j < 4; j++) {
                float2 a2 = *reinterpret_cast<float2*>(&acc[i][j]);
                v[j].x = a2.x + b[j].x;
                v[j].y = a2.y + b[j].y;
                if (do_leaky) {
                    v[j].x = v[j].x > 0.f ? v[j].x : 0.01f * v[j].x;
                    v[j].y = v[j].y > 0.f ? v[j].y : 0.01f * v[j].y;
                }
                cs[2 * j]     += v[j].x;
                cs[2 * j + 1] += v[j].y;
            }
            float4 o0 = make_float4(v[0].x, v[0].y, v[1].x, v[1].y);
            float4 o1 = make_float4(v[2].x, v[2].y, v[3].x, v[3].y);
            size_t base = (size_t)row * HD + tx * 8;
            *reinterpret_cast<float4*>(C + base)     = o0;
            *reinterpret_cast<float4*>(C + base + 4) = o1;
        }
    }

    // block-level colsum reduction in smem (reuse sW buffer 0 as [16][128])
    __syncthreads();
#pragma unroll
    for (int c = 0; c < 8; c++) sW[ty * 128 + tx * 8 + c] = cs[c];
    __syncthreads();
    if (t < 128) {
        float s = 0.f;
#pragma unroll
        for (int r = 0; r < 16; r++) s += sW[r * 128 + t];
        atomicAdd(&colsum_slot[t], s);
    }
}

// ---------------------------------------------------------------------------
// Readout: g = (colsum/N) @ Wpred + bpred ; logits = g @ Wcls + bcls ; softmax
// ---------------------------------------------------------------------------
__global__ void final_kernel(const float* __restrict__ colsum,
                             const float* __restrict__ Wpred, const float* __restrict__ bpred,
                             const float* __restrict__ Wcls,  const float* __restrict__ bcls,
                             float* __restrict__ out, float invn)
{
    __shared__ float g[HD];
    int t = threadIdx.x;   // 128 threads, one per hidden unit
    float acc = bpred[t];
    for (int k = 0; k < (NL + 1) * HD; k++)
        acc = fmaf(colsum[k] * invn, Wpred[k * HD + t], acc);
    g[t] = acc;
    __syncthreads();
    if (t == 0) {
        float l0 = bcls[0], l1 = bcls[1];
        for (int j = 0; j < HD; j++) {
            l0 = fmaf(g[j], Wcls[j * 2 + 0], l0);
            l1 = fmaf(g[j], Wcls[j * 2 + 1], l1);
        }
        float m  = fmaxf(l0, l1);
        float e0 = expf(l0 - m), e1 = expf(l1 - m);
        float inv = 1.0f / (e0 + e1);
        out[0] = e0 * inv;
        out[1] = e1 * inv;
    }
}

// ---------------------------------------------------------------------------
extern "C" void kernel_launch(void* const* d_in, const int* in_sizes, int n_in,
                              void* d_out, int out_size)
{
    const float* node_feat = (const float*)d_in[0];
    // d_in[1] edge_feat, d_in[2] base_data: unused by the reference graph
    const float* degree    = (const float*)d_in[3];
    const float* Wn        = (const float*)d_in[4];
    const float* bn        = (const float*)d_in[5];
    // d_in[6] We, d_in[7] be: edge projection is dead code
    const float* Wgcn      = (const float*)d_in[8];
    const float* bgcn      = (const float*)d_in[9];
    const float* Wpred     = (const float*)d_in[10];
    const float* bpred     = (const float*)d_in[11];
    const float* Wcls      = (const float*)d_in[12];
    const float* bcls      = (const float*)d_in[13];
    const int*   src       = (const int*)d_in[14];
    const int*   dst       = (const int*)d_in[15];

    const int n = in_sizes[3];    // degree has N elements
    const int e = in_sizes[14];   // src has E elements

    float *A, *B, *CS;
    int   *CNT;
    cudaGetSymbolAddress((void**)&A,   g_bufA);
    cudaGetSymbolAddress((void**)&B,   g_bufB);
    cudaGetSymbolAddress((void**)&CS,  g_colsum);
    cudaGetSymbolAddress((void**)&CNT, g_cnt);

    static bool attr_done = false;
    if (!attr_done) {
        cudaFuncSetAttribute(gemm_kernel<NFK>, cudaFuncAttributeMaxDynamicSharedMemorySize, GEMM_SMEM);
        cudaFuncSetAttribute(gemm_kernel<HD>,  cudaFuncAttributeMaxDynamicSharedMemorySize, GEMM_SMEM);
        attr_done = true;
    }

    const int gemm_blocks   = (n + 127) / 128;
    const int edge_blocks   = (e + 255) / 256;
    const int gather_blocks = (n + 7) / 8;      // 8 warps (nodes) per block

    // zero accumulators
    cudaMemsetAsync(CS, 0, (NL + 1) * HD * sizeof(float));
    cudaMemsetAsync(CNT, 0, NN * sizeof(int));

    // CSR build (per replay)
    hist_kernel<<<edge_blocks, 256>>>(dst, e);
    scan_kernel<<<1, 1024>>>(n);
    fill_kernel<<<edge_blocks, 256>>>(src, dst, degree, e);

    // h0 = node_feat @ Wn + bn -> A ; colsum slot 0
    gemm_kernel<NFK><<<gemm_blocks, 256, GEMM_SMEM>>>(node_feat, Wn, bn, A, CS, n, 0);

    // fusion: B[v] = sum_{u->v} h0[u]
    gather_kernel<0><<<gather_blocks, 256>>>((const float4*)A, (float4*)B, n);

    // 3 GCN layers: h in B; gather fuses self-term + degree scale into A
    for (int l = 0; l < NL; l++) {
        gather_kernel<1><<<gather_blocks, 256>>>((const float4*)B, (float4*)A, n);
        gemm_kernel<HD><<<gemm_blocks, 256, GEMM_SMEM>>>(A, Wgcn, bgcn, B, CS + (l + 1) * HD, n, 1);
    }

    final_kernel<<<1, HD>>>(CS, Wpred, bpred, Wcls, bcls, (float*)d_out, 1.0f / (float)n);
}

// round 5
// speedup vs baseline: 2.0696x; 1.0631x over previous
#include <cuda_runtime.h>
#include <cuda_bf16.h>

// Problem constants (fixed by the dataset)
#define NN   50000
#define EE   800000
#define NFK  256
#define HD   128
#define NL   3

typedef unsigned long long ull;

// Scratch: static device arrays (no runtime allocation allowed)
__device__ __align__(16) float g_bufA[NN * HD];     // 25.6 MB
__device__ __align__(16) float g_bufB[NN * HD];     // 25.6 MB
__device__ float g_colsum[(NL + 1) * HD];           // 512 floats
// CSR scratch
__device__ int   g_cnt[NN];
__device__ int   g_rowptr[NN + 1];
__device__ int   g_offs[NN];
__device__ int   g_esrc[EE];
__device__ float g_rscale[EE];

// Packed fp32x2 FMA (Blackwell): d = a*b + d elementwise on 2 packed floats.
__device__ __forceinline__ void ffma2(ull& d, ull a, ull b)
{
    asm("fma.rn.f32x2 %0, %1, %2, %3;" : "=l"(d) : "l"(a), "l"(b), "l"(d));
}

// cp.async 16B global->shared
__device__ __forceinline__ void cp16(void* smem, const void* g)
{
    unsigned sa = (unsigned)__cvta_generic_to_shared(smem);
    asm volatile("cp.async.cg.shared.global [%0], [%1], 16;" :: "r"(sa), "l"(g));
}
__device__ __forceinline__ void cp_commit() { asm volatile("cp.async.commit_group;"); }
__device__ __forceinline__ void cp_wait0()  { asm volatile("cp.async.wait_group 0;" ::: "memory"); }

// ---------------------------------------------------------------------------
// CSR build (per replay; order within a dst bucket is arbitrary)
// ---------------------------------------------------------------------------
__global__ void hist_kernel(const int* __restrict__ dst, int e)
{
    int i = blockIdx.x * blockDim.x + threadIdx.x;
    if (i < e) atomicAdd(&g_cnt[dst[i]], 1);
}

__global__ __launch_bounds__(1024)
void scan_kernel(int n)
{
    __shared__ int part[1024];
    int t = threadIdx.x;
    int chunk = (n + 1023) >> 10;
    int beg = t * chunk, end = min(beg + chunk, n);
    int s = 0;
    for (int i = beg; i < end; i++) s += g_cnt[i];
    part[t] = s;
    __syncthreads();
    for (int off = 1; off < 1024; off <<= 1) {
        int v = (t >= off) ? part[t - off] : 0;
        __syncthreads();
        part[t] += v;
        __syncthreads();
    }
    int run = part[t] - s;   // exclusive prefix of this thread's chunk
    for (int i = beg; i < end; i++) {
        g_rowptr[i] = run;
        g_offs[i]   = run;
        run += g_cnt[i];
    }
    if (end == n) g_rowptr[n] = run;
}

__global__ void fill_kernel(const int* __restrict__ src, const int* __restrict__ dst,
                            const float* __restrict__ degree, int e)
{
    int i = blockIdx.x * blockDim.x + threadIdx.x;
    if (i >= e) return;
    int s = src[i], d = dst[i];
    int pos = atomicAdd(&g_offs[d], 1);
    g_esrc[pos]   = s;
    g_rscale[pos] = 1.0f / degree[s];
}

// ---------------------------------------------------------------------------
// Gather: out[v] = (MODE ? h[v] : 0) + sum_{u->v} h[u] * (MODE ? 1/deg[u] : 1)
// One warp per node, lane = float4 column chunk. Unrolled x4 for MLP.
// ---------------------------------------------------------------------------
template <int MODE>
__global__ __launch_bounds__(256)
void gather_kernel(const float4* __restrict__ h, float4* __restrict__ out, int n)
{
    int w    = (blockIdx.x * blockDim.x + threadIdx.x) >> 5;
    int lane = threadIdx.x & 31;
    if (w >= n) return;
    int beg = g_rowptr[w], end = g_rowptr[w + 1];

    float4 acc;
    if (MODE) acc = h[(size_t)w * 32 + lane];
    else      acc = make_float4(0.f, 0.f, 0.f, 0.f);

    int i = beg;
    for (; i + 4 <= end; i += 4) {
        int s0 = g_esrc[i], s1 = g_esrc[i + 1], s2 = g_esrc[i + 2], s3 = g_esrc[i + 3];
        float4 x0 = h[(size_t)s0 * 32 + lane];
        float4 x1 = h[(size_t)s1 * 32 + lane];
        float4 x2 = h[(size_t)s2 * 32 + lane];
        float4 x3 = h[(size_t)s3 * 32 + lane];
        float c0 = 1.f, c1 = 1.f, c2 = 1.f, c3 = 1.f;
        if (MODE) { c0 = g_rscale[i]; c1 = g_rscale[i + 1]; c2 = g_rscale[i + 2]; c3 = g_rscale[i + 3]; }
        acc.x = fmaf(x0.x, c0, acc.x); acc.y = fmaf(x0.y, c0, acc.y);
        acc.z = fmaf(x0.z, c0, acc.z); acc.w = fmaf(x0.w, c0, acc.w);
        acc.x = fmaf(x1.x, c1, acc.x); acc.y = fmaf(x1.y, c1, acc.y);
        acc.z = fmaf(x1.z, c1, acc.z); acc.w = fmaf(x1.w, c1, acc.w);
        acc.x = fmaf(x2.x, c2, acc.x); acc.y = fmaf(x2.y, c2, acc.y);
        acc.z = fmaf(x2.z, c2, acc.z); acc.w = fmaf(x2.w, c2, acc.w);
        acc.x = fmaf(x3.x, c3, acc.x); acc.y = fmaf(x3.y, c3, acc.y);
        acc.z = fmaf(x3.z, c3, acc.z); acc.w = fmaf(x3.w, c3, acc.w);
    }
    for (; i < end; i++) {
        int s = g_esrc[i];
        float4 x = h[(size_t)s * 32 + lane];
        float c = MODE ? g_rscale[i] : 1.f;
        acc.x = fmaf(x.x, c, acc.x); acc.y = fmaf(x.y, c, acc.y);
        acc.z = fmaf(x.z, c, acc.z); acc.w = fmaf(x.w, c, acc.w);
    }
    out[(size_t)w * 32 + lane] = acc;
}

// ---------------------------------------------------------------------------
// GEMM: C[n x 128] = A[n x K] @ W[K x 128] + bias, optional leaky-ReLU,
// fused per-column sum.
// Tile 128x128, 512 threads, thread = 4 rows x 8 cols (4 column PAIRS at
// cols {2tx+32j, 2tx+32j+1} -> conflict-free 128B-contiguous wv loads).
// Double-buffered: W via cp.async, A via register prefetch, one sync/chunk.
// smem: sW[2][16*128] floats, sA[2][128*18] float2 (dup pairs, even stride
// so LDS is always 8B aligned).
// ---------------------------------------------------------------------------
#define SW_FLOATS (16 * 128)
#define SA_PAIRS  (128 * 18)
#define GEMM_SMEM (2 * SW_FLOATS * 4 + 2 * SA_PAIRS * 8)   // 53248 bytes

template <int K>
__global__ __launch_bounds__(512, 2)
void gemm_kernel(const float* __restrict__ A, const float* __restrict__ W,
                 const float* __restrict__ bias, float* __restrict__ C,
                 float* __restrict__ colsum_slot, int n, int do_leaky)
{
    extern __shared__ float smem_dyn[];
    float*  sW = smem_dyn;                            // 2 x 2048 floats
    float2* sA = (float2*)(smem_dyn + 2 * SW_FLOATS); // 2 x 2304 float2

    const int t    = threadIdx.x;
    const int tx   = t & 15;               // column pairs {2tx+32j, 2tx+32j+1}
    const int ty   = t >> 4;               // 0..31: rows [4*ty, 4*ty+3]
    const int row0 = blockIdx.x * 128;
    constexpr int NC = K / 16;

    // A staging geometry: thread stages one float4 (512 slots)
    const int r0  = t >> 2;                // local row 0..127
    const int kv0 = (t & 3) * 4;           // k offset within 16-chunk
    const int grow = row0 + r0;

    ull acc[4][4];
#pragma unroll
    for (int i = 0; i < 4; i++)
#pragma unroll
        for (int j = 0; j < 4; j++) acc[i][j] = 0ull;

    // ---- prologue: stage chunk 0 ----
    {
        const float4* Wv = reinterpret_cast<const float4*>(W);
        cp16(&reinterpret_cast<float4*>(sW)[t], Wv + t);
        cp_commit();
        float4 v = make_float4(0, 0, 0, 0);
        if (grow < n) v = *reinterpret_cast<const float4*>(A + (size_t)grow * K + kv0);
        float2* dp = &sA[r0 * 18];
        dp[kv0 + 0] = make_float2(v.x, v.x);
        dp[kv0 + 1] = make_float2(v.y, v.y);
        dp[kv0 + 2] = make_float2(v.z, v.z);
        dp[kv0 + 3] = make_float2(v.w, v.w);
        cp_wait0();
        __syncthreads();
    }

    for (int c = 0; c < NC; c++) {
        const int cur = c & 1, nxt = cur ^ 1;
        float4 v;
        const bool pre = (c + 1 < NC);
        if (pre) {
            const int k0n = (c + 1) * 16;
            const float4* Wv = reinterpret_cast<const float4*>(W + (size_t)k0n * HD);
            cp16(&reinterpret_cast<float4*>(sW + nxt * SW_FLOATS)[t], Wv + t);
            cp_commit();
            v = make_float4(0, 0, 0, 0);
            if (grow < n) v = *reinterpret_cast<const float4*>(A + (size_t)grow * K + k0n + kv0);
        }

        // ---- compute chunk 'cur' ----
        const float*  sWc = sW + cur * SW_FLOATS;
        const float2* sAc = sA + cur * SA_PAIRS;
#pragma unroll
        for (int kk = 0; kk < 16; kk++) {
            ull wv[4];
#pragma unroll
            for (int j = 0; j < 4; j++)
                wv[j] = *reinterpret_cast<const ull*>(&sWc[kk * 128 + 2 * tx + 32 * j]);
#pragma unroll
            for (int i = 0; i < 4; i++) {
                ull av = *reinterpret_cast<const ull*>(&sAc[(ty * 4 + i) * 18 + kk]);
#pragma unroll
                for (int j = 0; j < 4; j++) ffma2(acc[i][j], av, wv[j]);
            }
        }

        if (pre) {
            float2* dp = &sA[nxt * SA_PAIRS + r0 * 18];
            dp[kv0 + 0] = make_float2(v.x, v.x);
            dp[kv0 + 1] = make_float2(v.y, v.y);
            dp[kv0 + 2] = make_float2(v.z, v.z);
            dp[kv0 + 3] = make_float2(v.w, v.w);
            cp_wait0();
            __syncthreads();
        }
    }

    // ---- epilogue: bias, activation, store, colsum ----
    float2 b[4];
#pragma unroll
    for (int j = 0; j < 4; j++)
        b[j] = *reinterpret_cast<const float2*>(&bias[2 * tx + 32 * j]);

    float2 cs[4];
#pragma unroll
    for (int j = 0; j < 4; j++) cs[j] = make_float2(0.f, 0.f);

#pragma unroll
    for (int i = 0; i < 4; i++) {
        int row = row0 + ty * 4 + i;
        if (row < n) {
#pragma unroll
            for (int j = 0; j < 4; j++) {
                float2 a2 = *reinterpret_cast<float2*>(&acc[i][j]);
                float2 vv;
                vv.x = a2.x + b[j].x;
                vv.y = a2.y + b[j].y;
                if (do_leaky) {
                    vv.x = vv.x > 0.f ? vv.x : 0.01f * vv.x;
                    vv.y = vv.y > 0.f ? vv.y : 0.01f * vv.y;
                }
                cs[j].x += vv.x;
                cs[j].y += vv.y;
                *reinterpret_cast<float2*>(C + (size_t)row * HD + 2 * tx + 32 * j) = vv;
            }
        }
    }

    // block-level colsum reduction: sred[32][128] floats (reuse sW buffers)
    __syncthreads();
    float2* sred = reinterpret_cast<float2*>(sW);     // [32][64] float2
#pragma unroll
    for (int j = 0; j < 4; j++)
        sred[ty * 64 + tx + 16 * j] = cs[j];
    __syncthreads();
    if (t < 128) {
        // float slot t within a 128-float row; map slot -> actual column
        int pairidx = t >> 1, bit = t & 1;
        int stx = pairidx & 15, sj = pairidx >> 4;
        int col = 2 * stx + 32 * sj + bit;
        const float* sredf = reinterpret_cast<const float*>(sred);
        float s = 0.f;
#pragma unroll
        for (int r = 0; r < 32; r++) s += sredf[r * 128 + t];
        atomicAdd(&colsum_slot[col], s);
    }
}

// ---------------------------------------------------------------------------
// Readout: g = (colsum/N) @ Wpred + bpred ; logits = g @ Wcls + bcls ; softmax
// ---------------------------------------------------------------------------
__global__ void final_kernel(const float* __restrict__ colsum,
                             const float* __restrict__ Wpred, const float* __restrict__ bpred,
                             const float* __restrict__ Wcls,  const float* __restrict__ bcls,
                             float* __restrict__ out, float invn)
{
    __shared__ float g[HD];
    int t = threadIdx.x;   // 128 threads, one per hidden unit
    float acc = bpred[t];
    for (int k = 0; k < (NL + 1) * HD; k++)
        acc = fmaf(colsum[k] * invn, Wpred[k * HD + t], acc);
    g[t] = acc;
    __syncthreads();
    if (t == 0) {
        float l0 = bcls[0], l1 = bcls[1];
        for (int j = 0; j < HD; j++) {
            l0 = fmaf(g[j], Wcls[j * 2 + 0], l0);
            l1 = fmaf(g[j], Wcls[j * 2 + 1], l1);
        }
        float m  = fmaxf(l0, l1);
        float e0 = expf(l0 - m), e1 = expf(l1 - m);
        float inv = 1.0f / (e0 + e1);
        out[0] = e0 * inv;
        out[1] = e1 * inv;
    }
}

// ---------------------------------------------------------------------------
extern "C" void kernel_launch(void* const* d_in, const int* in_sizes, int n_in,
                              void* d_out, int out_size)
{
    const float* node_feat = (const float*)d_in[0];
    // d_in[1] edge_feat, d_in[2] base_data: unused by the reference graph
    const float* degree    = (const float*)d_in[3];
    const float* Wn        = (const float*)d_in[4];
    const float* bn        = (const float*)d_in[5];
    // d_in[6] We, d_in[7] be: edge projection is dead code
    const float* Wgcn      = (const float*)d_in[8];
    const float* bgcn      = (const float*)d_in[9];
    const float* Wpred     = (const float*)d_in[10];
    const float* bpred     = (const float*)d_in[11];
    const float* Wcls      = (const float*)d_in[12];
    const float* bcls      = (const float*)d_in[13];
    const int*   src       = (const int*)d_in[14];
    const int*   dst       = (const int*)d_in[15];

    const int n = in_sizes[3];    // degree has N elements
    const int e = in_sizes[14];   // src has E elements

    float *A, *B, *CS;
    int   *CNT;
    cudaGetSymbolAddress((void**)&A,   g_bufA);
    cudaGetSymbolAddress((void**)&B,   g_bufB);
    cudaGetSymbolAddress((void**)&CS,  g_colsum);
    cudaGetSymbolAddress((void**)&CNT, g_cnt);

    static bool init_done = false;
    static cudaStream_t s2;
    static cudaEvent_t ev_fork, ev_join;
    if (!init_done) {
        cudaFuncSetAttribute(gemm_kernel<NFK>, cudaFuncAttributeMaxDynamicSharedMemorySize, GEMM_SMEM);
        cudaFuncSetAttribute(gemm_kernel<HD>,  cudaFuncAttributeMaxDynamicSharedMemorySize, GEMM_SMEM);
        cudaStreamCreateWithFlags(&s2, cudaStreamNonBlocking);
        cudaEventCreateWithFlags(&ev_fork, cudaEventDisableTiming);
        cudaEventCreateWithFlags(&ev_join, cudaEventDisableTiming);
        init_done = true;
    }

    const int gemm_blocks   = (n + 127) / 128;
    const int edge_blocks   = (e + 255) / 256;
    const int gather_blocks = (n + 7) / 8;      // 8 warps (nodes) per block

    // ---- fork: CSR build on s2, overlapped with the big input GEMM ----
    cudaEventRecord(ev_fork, 0);
    cudaStreamWaitEvent(s2, ev_fork, 0);

    cudaMemsetAsync(CNT, 0, NN * sizeof(int), s2);
    hist_kernel<<<edge_blocks, 256, 0, s2>>>(dst, e);
    scan_kernel<<<1, 1024, 0, s2>>>(n);
    fill_kernel<<<edge_blocks, 256, 0, s2>>>(src, dst, degree, e);
    cudaEventRecord(ev_join, s2);

    // main stream: colsum zero + h0 = node_feat @ Wn + bn -> A
    cudaMemsetAsync(CS, 0, (NL + 1) * HD * sizeof(float));
    gemm_kernel<NFK><<<gemm_blocks, 512, GEMM_SMEM>>>(node_feat, Wn, bn, A, CS, n, 0);

    // join: gathers need both the CSR and A
    cudaStreamWaitEvent(0, ev_join, 0);

    // fusion: B[v] = sum_{u->v} h0[u]
    gather_kernel<0><<<gather_blocks, 256>>>((const float4*)A, (float4*)B, n);

    // 3 GCN layers: h in B; gather fuses self-term + degree scale into A
    for (int l = 0; l < NL; l++) {
        gather_kernel<1><<<gather_blocks, 256>>>((const float4*)B, (float4*)A, n);
        gemm_kernel<HD><<<gemm_blocks, 512, GEMM_SMEM>>>(A, Wgcn, bgcn, B, CS + (l + 1) * HD, n, 1);
    }

    final_kernel<<<1, HD>>>(CS, Wpred, bpred, Wcls, bcls, (float*)d_out, 1.0f / (float)n);
}

// round 6
// speedup vs baseline: 2.1697x; 1.0484x over previous
#include <cuda_runtime.h>
#include <cuda_bf16.h>

// Problem constants (fixed by the dataset)
#define NN   50000
#define EE   800000
#define NFK  256
#define HD   128
#define NL   3

typedef unsigned long long ull;

// Scratch: static device arrays (no runtime allocation allowed)
__device__ __align__(16) float g_bufA[NN * HD];     // 25.6 MB
__device__ __align__(16) float g_bufB[NN * HD];     // 25.6 MB
__device__ float g_colsum[(NL + 1) * HD];           // 512 floats
// CSR scratch
__device__ int   g_cnt[NN];
__device__ int   g_rowptr[NN + 1];
__device__ int   g_offs[NN];
__device__ int   g_esrc[EE];
__device__ float g_rscale[EE];

// Packed fp32x2 FMA (Blackwell): d = a*b + d elementwise on 2 packed floats.
__device__ __forceinline__ void ffma2(ull& d, ull a, ull b)
{
    asm("fma.rn.f32x2 %0, %1, %2, %3;" : "=l"(d) : "l"(a), "l"(b), "l"(d));
}

// cp.async 16B global->shared
__device__ __forceinline__ void cp16(void* smem, const void* g)
{
    unsigned sa = (unsigned)__cvta_generic_to_shared(smem);
    asm volatile("cp.async.cg.shared.global [%0], [%1], 16;" :: "r"(sa), "l"(g));
}
__device__ __forceinline__ void cp_commit() { asm volatile("cp.async.commit_group;"); }
__device__ __forceinline__ void cp_wait0()  { asm volatile("cp.async.wait_group 0;" ::: "memory"); }

// ---------------------------------------------------------------------------
// CSR build (per replay; order within a dst bucket is arbitrary)
// ---------------------------------------------------------------------------
__global__ void hist_kernel(const int* __restrict__ dst, int e)
{
    int i = blockIdx.x * blockDim.x + threadIdx.x;
    if (i < e) atomicAdd(&g_cnt[dst[i]], 1);
}

__global__ __launch_bounds__(1024)
void scan_kernel(int n)
{
    __shared__ int part[1024];
    int t = threadIdx.x;
    int chunk = (n + 1023) >> 10;
    int beg = t * chunk, end = min(beg + chunk, n);
    int s = 0;
    for (int i = beg; i < end; i++) s += g_cnt[i];
    part[t] = s;
    __syncthreads();
    for (int off = 1; off < 1024; off <<= 1) {
        int v = (t >= off) ? part[t - off] : 0;
        __syncthreads();
        part[t] += v;
        __syncthreads();
    }
    int run = part[t] - s;   // exclusive prefix of this thread's chunk
    for (int i = beg; i < end; i++) {
        g_rowptr[i] = run;
        g_offs[i]   = run;
        run += g_cnt[i];
    }
    if (end == n) g_rowptr[n] = run;
}

__global__ void fill_kernel(const int* __restrict__ src, const int* __restrict__ dst,
                            const float* __restrict__ degree, int e)
{
    int i = blockIdx.x * blockDim.x + threadIdx.x;
    if (i >= e) return;
    int s = src[i], d = dst[i];
    int pos = atomicAdd(&g_offs[d], 1);
    g_esrc[pos]   = s;
    g_rscale[pos] = 1.0f / degree[s];
}

// ---------------------------------------------------------------------------
// Gather: out[v] = (MODE ? h[v] : 0) + sum_{u->v} h[u] * (MODE ? 1/deg[u] : 1)
// One warp per node, lane = float4 column chunk. Unrolled x4 for MLP.
// ---------------------------------------------------------------------------
template <int MODE>
__global__ __launch_bounds__(256)
void gather_kernel(const float4* __restrict__ h, float4* __restrict__ out, int n)
{
    int w    = (blockIdx.x * blockDim.x + threadIdx.x) >> 5;
    int lane = threadIdx.x & 31;
    if (w >= n) return;
    int beg = g_rowptr[w], end = g_rowptr[w + 1];

    float4 acc;
    if (MODE) acc = h[(size_t)w * 32 + lane];
    else      acc = make_float4(0.f, 0.f, 0.f, 0.f);

    int i = beg;
    for (; i + 4 <= end; i += 4) {
        int s0 = g_esrc[i], s1 = g_esrc[i + 1], s2 = g_esrc[i + 2], s3 = g_esrc[i + 3];
        float4 x0 = h[(size_t)s0 * 32 + lane];
        float4 x1 = h[(size_t)s1 * 32 + lane];
        float4 x2 = h[(size_t)s2 * 32 + lane];
        float4 x3 = h[(size_t)s3 * 32 + lane];
        float c0 = 1.f, c1 = 1.f, c2 = 1.f, c3 = 1.f;
        if (MODE) { c0 = g_rscale[i]; c1 = g_rscale[i + 1]; c2 = g_rscale[i + 2]; c3 = g_rscale[i + 3]; }
        acc.x = fmaf(x0.x, c0, acc.x); acc.y = fmaf(x0.y, c0, acc.y);
        acc.z = fmaf(x0.z, c0, acc.z); acc.w = fmaf(x0.w, c0, acc.w);
        acc.x = fmaf(x1.x, c1, acc.x); acc.y = fmaf(x1.y, c1, acc.y);
        acc.z = fmaf(x1.z, c1, acc.z); acc.w = fmaf(x1.w, c1, acc.w);
        acc.x = fmaf(x2.x, c2, acc.x); acc.y = fmaf(x2.y, c2, acc.y);
        acc.z = fmaf(x2.z, c2, acc.z); acc.w = fmaf(x2.w, c2, acc.w);
        acc.x = fmaf(x3.x, c3, acc.x); acc.y = fmaf(x3.y, c3, acc.y);
        acc.z = fmaf(x3.z, c3, acc.z); acc.w = fmaf(x3.w, c3, acc.w);
    }
    for (; i < end; i++) {
        int s = g_esrc[i];
        float4 x = h[(size_t)s * 32 + lane];
        float c = MODE ? g_rscale[i] : 1.f;
        acc.x = fmaf(x.x, c, acc.x); acc.y = fmaf(x.y, c, acc.y);
        acc.z = fmaf(x.z, c, acc.z); acc.w = fmaf(x.w, c, acc.w);
    }
    out[(size_t)w * 32 + lane] = acc;
}

// ---------------------------------------------------------------------------
// GEMM: C[n x 128] = A[n x K] @ W[K x 128] + bias, optional leaky-ReLU,
// fused per-column sum.
// Tile 128x128, 256 threads, thread = 8 rows x 8 cols (column PAIRS at
// {2tx+32j, 2tx+32j+1} -> conflict-free 128B-contiguous wv loads).
// av loads vectorized: duplicated A pairs for (kk, kk+1) read as one LDS.128
// (broadcast) -> crossbar demand ~50%, FMA pipe becomes the limiter.
// Double-buffered: W via cp.async, A via register prefetch, one sync/chunk.
// smem: sW[2][16*128] floats, sA[2][128*20] float2 (row stride 20 pairs =
// 160B, 16B-aligned so LDS.128 works on every row).
// ---------------------------------------------------------------------------
#define SW_FLOATS (16 * 128)
#define SA_PAIRS  (128 * 20)
#define GEMM_SMEM (2 * SW_FLOATS * 4 + 2 * SA_PAIRS * 8)   // 57344 bytes

template <int K>
__global__ __launch_bounds__(256, 2)
void gemm_kernel(const float* __restrict__ A, const float* __restrict__ W,
                 const float* __restrict__ bias, float* __restrict__ C,
                 float* __restrict__ colsum_slot, int n, int do_leaky)
{
    extern __shared__ float smem_dyn[];
    float*  sW = smem_dyn;                            // 2 x 2048 floats
    float2* sA = (float2*)(smem_dyn + 2 * SW_FLOATS); // 2 x 2560 float2

    const int t    = threadIdx.x;
    const int tx   = t & 15;               // column pairs {2tx+32j, 2tx+32j+1}
    const int ty   = t >> 4;               // 0..15: rows [8*ty, 8*ty+7]
    const int row0 = blockIdx.x * 128;
    constexpr int NC = K / 16;

    // A staging geometry: thread stages two float4 (512 slots)
    const int f0 = t,       r0 = f0 >> 2, kv0 = (f0 & 3) * 4;
    const int f1 = t + 256, r1 = f1 >> 2, kv1 = (f1 & 3) * 4;
    const int grow0 = row0 + r0, grow1 = row0 + r1;

    ull acc[8][4];
#pragma unroll
    for (int i = 0; i < 8; i++)
#pragma unroll
        for (int j = 0; j < 4; j++) acc[i][j] = 0ull;

    // ---- prologue: stage chunk 0 ----
    {
        const float4* Wv = reinterpret_cast<const float4*>(W);
        cp16(&reinterpret_cast<float4*>(sW)[t], Wv + t);
        cp16(&reinterpret_cast<float4*>(sW)[t + 256], Wv + t + 256);
        cp_commit();
        float4 v0 = make_float4(0, 0, 0, 0), v1 = make_float4(0, 0, 0, 0);
        if (grow0 < n) v0 = *reinterpret_cast<const float4*>(A + (size_t)grow0 * K + kv0);
        if (grow1 < n) v1 = *reinterpret_cast<const float4*>(A + (size_t)grow1 * K + kv1);
        float2* dp0 = &sA[r0 * 20];
        dp0[kv0 + 0] = make_float2(v0.x, v0.x); dp0[kv0 + 1] = make_float2(v0.y, v0.y);
        dp0[kv0 + 2] = make_float2(v0.z, v0.z); dp0[kv0 + 3] = make_float2(v0.w, v0.w);
        float2* dp1 = &sA[r1 * 20];
        dp1[kv1 + 0] = make_float2(v1.x, v1.x); dp1[kv1 + 1] = make_float2(v1.y, v1.y);
        dp1[kv1 + 2] = make_float2(v1.z, v1.z); dp1[kv1 + 3] = make_float2(v1.w, v1.w);
        cp_wait0();
        __syncthreads();
    }

    for (int c = 0; c < NC; c++) {
        const int cur = c & 1, nxt = cur ^ 1;
        float4 v0, v1;
        const bool pre = (c + 1 < NC);
        if (pre) {
            const int k0n = (c + 1) * 16;
            const float4* Wv = reinterpret_cast<const float4*>(W + (size_t)k0n * HD);
            float4* sWn = reinterpret_cast<float4*>(sW + nxt * SW_FLOATS);
            cp16(&sWn[t], Wv + t);
            cp16(&sWn[t + 256], Wv + t + 256);
            cp_commit();
            v0 = make_float4(0, 0, 0, 0); v1 = make_float4(0, 0, 0, 0);
            if (grow0 < n) v0 = *reinterpret_cast<const float4*>(A + (size_t)grow0 * K + k0n + kv0);
            if (grow1 < n) v1 = *reinterpret_cast<const float4*>(A + (size_t)grow1 * K + k0n + kv1);
        }

        // ---- compute chunk 'cur' (2 k-steps per iteration) ----
        const float*  sWc = sW + cur * SW_FLOATS;
        const float2* sAc = sA + cur * SA_PAIRS;
#pragma unroll
        for (int kk = 0; kk < 16; kk += 2) {
            ull wv0[4], wv1[4];
#pragma unroll
            for (int j = 0; j < 4; j++) {
                wv0[j] = *reinterpret_cast<const ull*>(&sWc[kk * 128 + 2 * tx + 32 * j]);
                wv1[j] = *reinterpret_cast<const ull*>(&sWc[(kk + 1) * 128 + 2 * tx + 32 * j]);
            }
#pragma unroll
            for (int i = 0; i < 8; i++) {
                // one LDS.128: duplicated pairs for kk and kk+1 (16B aligned:
                // row stride 160B, kk even -> offset multiple of 16)
                ulonglong2 av = *reinterpret_cast<const ulonglong2*>(
                                    &sAc[(ty * 8 + i) * 20 + kk]);
#pragma unroll
                for (int j = 0; j < 4; j++) ffma2(acc[i][j], av.x, wv0[j]);
#pragma unroll
                for (int j = 0; j < 4; j++) ffma2(acc[i][j], av.y, wv1[j]);
            }
        }

        if (pre) {
            float2* dp0 = &sA[nxt * SA_PAIRS + r0 * 20];
            dp0[kv0 + 0] = make_float2(v0.x, v0.x); dp0[kv0 + 1] = make_float2(v0.y, v0.y);
            dp0[kv0 + 2] = make_float2(v0.z, v0.z); dp0[kv0 + 3] = make_float2(v0.w, v0.w);
            float2* dp1 = &sA[nxt * SA_PAIRS + r1 * 20];
            dp1[kv1 + 0] = make_float2(v1.x, v1.x); dp1[kv1 + 1] = make_float2(v1.y, v1.y);
            dp1[kv1 + 2] = make_float2(v1.z, v1.z); dp1[kv1 + 3] = make_float2(v1.w, v1.w);
            cp_wait0();
            __syncthreads();
        }
    }

    // ---- epilogue: bias, activation, store, colsum ----
    float2 b[4];
#pragma unroll
    for (int j = 0; j < 4; j++)
        b[j] = *reinterpret_cast<const float2*>(&bias[2 * tx + 32 * j]);

    float2 cs[4];
#pragma unroll
    for (int j = 0; j < 4; j++) cs[j] = make_float2(0.f, 0.f);

#pragma unroll
    for (int i = 0; i < 8; i++) {
        int row = row0 + ty * 8 + i;
        if (row < n) {
#pragma unroll
            for (int j = 0; j < 4; j++) {
                float2 a2 = *reinterpret_cast<float2*>(&acc[i][j]);
                float2 vv;
                vv.x = a2.x + b[j].x;
                vv.y = a2.y + b[j].y;
                if (do_leaky) {
                    vv.x = vv.x > 0.f ? vv.x : 0.01f * vv.x;
                    vv.y = vv.y > 0.f ? vv.y : 0.01f * vv.y;
                }
                cs[j].x += vv.x;
                cs[j].y += vv.y;
                *reinterpret_cast<float2*>(C + (size_t)row * HD + 2 * tx + 32 * j) = vv;
            }
        }
    }

    // block-level colsum reduction: sred[16][128] floats (reuse sW buffers)
    __syncthreads();
    float* sred = sW;
#pragma unroll
    for (int j = 0; j < 4; j++) {
        sred[ty * 128 + 2 * tx + 32 * j]     = cs[j].x;
        sred[ty * 128 + 2 * tx + 32 * j + 1] = cs[j].y;
    }
    __syncthreads();
    if (t < 128) {
        float s = 0.f;
#pragma unroll
        for (int r = 0; r < 16; r++) s += sred[r * 128 + t];
        atomicAdd(&colsum_slot[t], s);
    }
}

// ---------------------------------------------------------------------------
// Readout: g = (colsum/N) @ Wpred + bpred ; logits = g @ Wcls + bcls ; softmax
// ---------------------------------------------------------------------------
__global__ void final_kernel(const float* __restrict__ colsum,
                             const float* __restrict__ Wpred, const float* __restrict__ bpred,
                             const float* __restrict__ Wcls,  const float* __restrict__ bcls,
                             float* __restrict__ out, float invn)
{
    __shared__ float g[HD];
    int t = threadIdx.x;   // 128 threads, one per hidden unit
    float acc = bpred[t];
    for (int k = 0; k < (NL + 1) * HD; k++)
        acc = fmaf(colsum[k] * invn, Wpred[k * HD + t], acc);
    g[t] = acc;
    __syncthreads();
    if (t == 0) {
        float l0 = bcls[0], l1 = bcls[1];
        for (int j = 0; j < HD; j++) {
            l0 = fmaf(g[j], Wcls[j * 2 + 0], l0);
            l1 = fmaf(g[j], Wcls[j * 2 + 1], l1);
        }
        float m  = fmaxf(l0, l1);
        float e0 = expf(l0 - m), e1 = expf(l1 - m);
        float inv = 1.0f / (e0 + e1);
        out[0] = e0 * inv;
        out[1] = e1 * inv;
    }
}

// ---------------------------------------------------------------------------
extern "C" void kernel_launch(void* const* d_in, const int* in_sizes, int n_in,
                              void* d_out, int out_size)
{
    const float* node_feat = (const float*)d_in[0];
    // d_in[1] edge_feat, d_in[2] base_data: unused by the reference graph
    const float* degree    = (const float*)d_in[3];
    const float* Wn        = (const float*)d_in[4];
    const float* bn        = (const float*)d_in[5];
    // d_in[6] We, d_in[7] be: edge projection is dead code
    const float* Wgcn      = (const float*)d_in[8];
    const float* bgcn      = (const float*)d_in[9];
    const float* Wpred     = (const float*)d_in[10];
    const float* bpred     = (const float*)d_in[11];
    const float* Wcls      = (const float*)d_in[12];
    const float* bcls      = (const float*)d_in[13];
    const int*   src       = (const int*)d_in[14];
    const int*   dst       = (const int*)d_in[15];

    const int n = in_sizes[3];    // degree has N elements
    const int e = in_sizes[14];   // src has E elements

    float *A, *B, *CS;
    int   *CNT;
    cudaGetSymbolAddress((void**)&A,   g_bufA);
    cudaGetSymbolAddress((void**)&B,   g_bufB);
    cudaGetSymbolAddress((void**)&CS,  g_colsum);
    cudaGetSymbolAddress((void**)&CNT, g_cnt);

    static bool init_done = false;
    static cudaStream_t s2;
    static cudaEvent_t ev_fork, ev_join;
    if (!init_done) {
        cudaFuncSetAttribute(gemm_kernel<NFK>, cudaFuncAttributeMaxDynamicSharedMemorySize, GEMM_SMEM);
        cudaFuncSetAttribute(gemm_kernel<HD>,  cudaFuncAttributeMaxDynamicSharedMemorySize, GEMM_SMEM);
        cudaStreamCreateWithFlags(&s2, cudaStreamNonBlocking);
        cudaEventCreateWithFlags(&ev_fork, cudaEventDisableTiming);
        cudaEventCreateWithFlags(&ev_join, cudaEventDisableTiming);
        init_done = true;
    }

    const int gemm_blocks   = (n + 127) / 128;
    const int edge_blocks   = (e + 255) / 256;
    const int gather_blocks = (n + 7) / 8;      // 8 warps (nodes) per block

    // ---- fork: CSR build on s2, overlapped with the big input GEMM ----
    cudaEventRecord(ev_fork, 0);
    cudaStreamWaitEvent(s2, ev_fork, 0);

    cudaMemsetAsync(CNT, 0, NN * sizeof(int), s2);
    hist_kernel<<<edge_blocks, 256, 0, s2>>>(dst, e);
    scan_kernel<<<1, 1024, 0, s2>>>(n);
    fill_kernel<<<edge_blocks, 256, 0, s2>>>(src, dst, degree, e);
    cudaEventRecord(ev_join, s2);

    // main stream: colsum zero + h0 = node_feat @ Wn + bn -> A
    cudaMemsetAsync(CS, 0, (NL + 1) * HD * sizeof(float));
    gemm_kernel<NFK><<<gemm_blocks, 256, GEMM_SMEM>>>(node_feat, Wn, bn, A, CS, n, 0);

    // join: gathers need both the CSR and A
    cudaStreamWaitEvent(0, ev_join, 0);

    // fusion: B[v] = sum_{u->v} h0[u]
    gather_kernel<0><<<gather_blocks, 256>>>((const float4*)A, (float4*)B, n);

    // 3 GCN layers: h in B; gather fuses self-term + degree scale into A
    for (int l = 0; l < NL; l++) {
        gather_kernel<1><<<gather_blocks, 256>>>((const float4*)B, (float4*)A, n);
        gemm_kernel<HD><<<gemm_blocks, 256, GEMM_SMEM>>>(A, Wgcn, bgcn, B, CS + (l + 1) * HD, n, 1);
    }

    final_kernel<<<1, HD>>>(CS, Wpred, bpred, Wcls, bcls, (float*)d_out, 1.0f / (float)n);
}

// round 8
// speedup vs baseline: 2.2299x; 1.0278x over previous
#include <cuda_runtime.h>
#include <cuda_bf16.h>
#include <cstdint>

// Problem constants (fixed by the dataset)
#define NN   50000
#define EE   800000
#define NFK  256
#define HD   128
#define NL   3

typedef unsigned long long ull;

// Scratch: static device arrays (no runtime allocation allowed)
__device__ __align__(16) float g_bufA[NN * HD];             // fp32 agg (25.6 MB)
__device__ __align__(16) __nv_bfloat16 g_h0[NN * HD];       // bf16 h ping (12.8 MB)
__device__ __align__(16) __nv_bfloat16 g_h1[NN * HD];       // bf16 h pong (12.8 MB)
__device__ float g_colsum[(NL + 1) * HD];                   // 512 floats
// CSR scratch
__device__ int   g_cnt[NN];
__device__ int   g_rowptr[NN + 1];
__device__ int   g_offs[NN];
__device__ int   g_esrc[EE];
__device__ float g_rscale[EE];

// Packed fp32x2 FMA (Blackwell): d = a*b + d elementwise on 2 packed floats.
__device__ __forceinline__ void ffma2(ull& d, ull a, ull b)
{
    asm("fma.rn.f32x2 %0, %1, %2, %3;" : "=l"(d) : "l"(a), "l"(b), "l"(d));
}

// cp.async 16B global->shared
__device__ __forceinline__ void cp16(void* smem, const void* g)
{
    unsigned sa = (unsigned)__cvta_generic_to_shared(smem);
    asm volatile("cp.async.cg.shared.global [%0], [%1], 16;" :: "r"(sa), "l"(g));
}
__device__ __forceinline__ void cp_commit() { asm volatile("cp.async.commit_group;"); }
__device__ __forceinline__ void cp_wait0()  { asm volatile("cp.async.wait_group 0;" ::: "memory"); }

// ---------------------------------------------------------------------------
// CSR build (per replay; order within a dst bucket is arbitrary)
// ---------------------------------------------------------------------------
__global__ void hist_kernel(const int* __restrict__ dst, int e)
{
    int i = blockIdx.x * blockDim.x + threadIdx.x;
    if (i < e) atomicAdd(&g_cnt[dst[i]], 1);
}

__global__ __launch_bounds__(1024)
void scan_kernel(int n)
{
    __shared__ int part[1024];
    int t = threadIdx.x;
    int chunk = (n + 1023) >> 10;
    int beg = t * chunk, end = min(beg + chunk, n);
    int s = 0;
    for (int i = beg; i < end; i++) s += g_cnt[i];
    part[t] = s;
    __syncthreads();
    for (int off = 1; off < 1024; off <<= 1) {
        int v = (t >= off) ? part[t - off] : 0;
        __syncthreads();
        part[t] += v;
        __syncthreads();
    }
    int run = part[t] - s;
    for (int i = beg; i < end; i++) {
        g_rowptr[i] = run;
        g_offs[i]   = run;
        run += g_cnt[i];
    }
    if (end == n) g_rowptr[n] = run;
}

__global__ void fill_kernel(const int* __restrict__ src, const int* __restrict__ dst,
                            const float* __restrict__ degree, int e)
{
    int i = blockIdx.x * blockDim.x + threadIdx.x;
    if (i >= e) return;
    int s = src[i], d = dst[i];
    int pos = atomicAdd(&g_offs[d], 1);
    g_esrc[pos]   = s;
    g_rscale[pos] = 1.0f / degree[s];
}

// ---------------------------------------------------------------------------
// Gather over bf16 hidden states, fp32 accumulation.
// MODE 0 (fusion):   out_bf16[v] = sum_{u->v} h[u]
// MODE 1 (gcn prop): out_f32[v]  = h[v] + sum_{u->v} h[u] * (1/deg[u])
// One warp per node; lane owns 4 columns (one LDG.64 of 4 bf16 per edge).
// ---------------------------------------------------------------------------
__device__ __forceinline__ void acc_bf(float4& acc, ull x, float c)
{
    const __nv_bfloat162* p = reinterpret_cast<const __nv_bfloat162*>(&x);
    float2 f0 = __bfloat1622float2(p[0]);
    float2 f1 = __bfloat1622float2(p[1]);
    acc.x = fmaf(f0.x, c, acc.x); acc.y = fmaf(f0.y, c, acc.y);
    acc.z = fmaf(f1.x, c, acc.z); acc.w = fmaf(f1.y, c, acc.w);
}

template <int MODE>
__global__ __launch_bounds__(256)
void gather_kernel(const ull* __restrict__ h, void* __restrict__ out_, int n)
{
    int w    = (blockIdx.x * blockDim.x + threadIdx.x) >> 5;
    int lane = threadIdx.x & 31;
    if (w >= n) return;
    int beg = g_rowptr[w], end = g_rowptr[w + 1];

    float4 acc = make_float4(0.f, 0.f, 0.f, 0.f);
    if (MODE) {
        ull sv = h[(size_t)w * 32 + lane];
        acc_bf(acc, sv, 1.0f);
    }

    int i = beg;
    for (; i + 4 <= end; i += 4) {
        int s0 = g_esrc[i], s1 = g_esrc[i + 1], s2 = g_esrc[i + 2], s3 = g_esrc[i + 3];
        ull x0 = h[(size_t)s0 * 32 + lane];
        ull x1 = h[(size_t)s1 * 32 + lane];
        ull x2 = h[(size_t)s2 * 32 + lane];
        ull x3 = h[(size_t)s3 * 32 + lane];
        float c0 = 1.f, c1 = 1.f, c2 = 1.f, c3 = 1.f;
        if (MODE) { c0 = g_rscale[i]; c1 = g_rscale[i + 1]; c2 = g_rscale[i + 2]; c3 = g_rscale[i + 3]; }
        acc_bf(acc, x0, c0);
        acc_bf(acc, x1, c1);
        acc_bf(acc, x2, c2);
        acc_bf(acc, x3, c3);
    }
    for (; i < end; i++) {
        int s = g_esrc[i];
        ull x = h[(size_t)s * 32 + lane];
        float c = MODE ? g_rscale[i] : 1.f;
        acc_bf(acc, x, c);
    }

    if (MODE) {
        // fp32 output (GEMM input)
        reinterpret_cast<float4*>(out_)[(size_t)w * 32 + lane] = acc;
    } else {
        // bf16 output
        __nv_bfloat162 o0 = __floats2bfloat162_rn(acc.x, acc.y);
        __nv_bfloat162 o1 = __floats2bfloat162_rn(acc.z, acc.w);
        ull packed = (ull)*reinterpret_cast<unsigned*>(&o0)
                   | ((ull)*reinterpret_cast<unsigned*>(&o1) << 32);
        reinterpret_cast<ull*>(out_)[(size_t)w * 32 + lane] = packed;
    }
}

// ---------------------------------------------------------------------------
// GEMM: C_bf16[n x 128] = A_f32[n x K] @ W[K x 128] + bias, optional leaky,
// fused per-column sum (computed from fp32 pre-quantization values).
// Tile 128x128, 256 threads, thread = 8 rows x 8 cols (column PAIRS at
// {2tx+32j, 2tx+32j+1}); wv loads conflict-free 128B-contiguous; av loads
// LDS.128 covering 2 k-steps. Double-buffered (cp.async W, reg-prefetch A).
// STORE=0 skips the C store (last layer: only colsum needed).
// ---------------------------------------------------------------------------
#define SW_FLOATS (16 * 128)
#define SA_PAIRS  (128 * 20)
#define GEMM_SMEM (2 * SW_FLOATS * 4 + 2 * SA_PAIRS * 8)   // 57344 bytes

template <int K, int STORE>
__global__ __launch_bounds__(256, 2)
void gemm_kernel(const float* __restrict__ A, const float* __restrict__ W,
                 const float* __restrict__ bias, __nv_bfloat16* __restrict__ C,
                 float* __restrict__ colsum_slot, int n, int do_leaky)
{
    extern __shared__ float smem_dyn[];
    float*  sW = smem_dyn;                            // 2 x 2048 floats
    float2* sA = (float2*)(smem_dyn + 2 * SW_FLOATS); // 2 x 2560 float2

    const int t    = threadIdx.x;
    const int tx   = t & 15;               // column pairs {2tx+32j, 2tx+32j+1}
    const int ty   = t >> 4;               // 0..15: rows [8*ty, 8*ty+7]
    const int row0 = blockIdx.x * 128;
    constexpr int NC = K / 16;

    // A staging geometry: thread stages two float4 (512 slots)
    const int f0 = t,       r0 = f0 >> 2, kv0 = (f0 & 3) * 4;
    const int f1 = t + 256, r1 = f1 >> 2, kv1 = (f1 & 3) * 4;
    const int grow0 = row0 + r0, grow1 = row0 + r1;

    ull acc[8][4];
#pragma unroll
    for (int i = 0; i < 8; i++)
#pragma unroll
        for (int j = 0; j < 4; j++) acc[i][j] = 0ull;

    // ---- prologue: stage chunk 0 ----
    {
        const float4* Wv = reinterpret_cast<const float4*>(W);
        cp16(&reinterpret_cast<float4*>(sW)[t], Wv + t);
        cp16(&reinterpret_cast<float4*>(sW)[t + 256], Wv + t + 256);
        cp_commit();
        float4 v0 = make_float4(0, 0, 0, 0), v1 = make_float4(0, 0, 0, 0);
        if (grow0 < n) v0 = *reinterpret_cast<const float4*>(A + (size_t)grow0 * K + kv0);
        if (grow1 < n) v1 = *reinterpret_cast<const float4*>(A + (size_t)grow1 * K + kv1);
        float2* dp0 = &sA[r0 * 20];
        dp0[kv0 + 0] = make_float2(v0.x, v0.x); dp0[kv0 + 1] = make_float2(v0.y, v0.y);
        dp0[kv0 + 2] = make_float2(v0.z, v0.z); dp0[kv0 + 3] = make_float2(v0.w, v0.w);
        float2* dp1 = &sA[r1 * 20];
        dp1[kv1 + 0] = make_float2(v1.x, v1.x); dp1[kv1 + 1] = make_float2(v1.y, v1.y);
        dp1[kv1 + 2] = make_float2(v1.z, v1.z); dp1[kv1 + 3] = make_float2(v1.w, v1.w);
        cp_wait0();
        __syncthreads();
    }

    for (int c = 0; c < NC; c++) {
        const int cur = c & 1, nxt = cur ^ 1;
        float4 v0, v1;
        const bool pre = (c + 1 < NC);
        if (pre) {
            const int k0n = (c + 1) * 16;
            const float4* Wv = reinterpret_cast<const float4*>(W + (size_t)k0n * HD);
            float4* sWn = reinterpret_cast<float4*>(sW + nxt * SW_FLOATS);
            cp16(&sWn[t], Wv + t);
            cp16(&sWn[t + 256], Wv + t + 256);
            cp_commit();
            v0 = make_float4(0, 0, 0, 0); v1 = make_float4(0, 0, 0, 0);
            if (grow0 < n) v0 = *reinterpret_cast<const float4*>(A + (size_t)grow0 * K + k0n + kv0);
            if (grow1 < n) v1 = *reinterpret_cast<const float4*>(A + (size_t)grow1 * K + k0n + kv1);
        }

        // ---- compute chunk 'cur' (2 k-steps per iteration) ----
        const float*  sWc = sW + cur * SW_FLOATS;
        const float2* sAc = sA + cur * SA_PAIRS;
#pragma unroll
        for (int kk = 0; kk < 16; kk += 2) {
            ull wv0[4], wv1[4];
#pragma unroll
            for (int j = 0; j < 4; j++) {
                wv0[j] = *reinterpret_cast<const ull*>(&sWc[kk * 128 + 2 * tx + 32 * j]);
                wv1[j] = *reinterpret_cast<const ull*>(&sWc[(kk + 1) * 128 + 2 * tx + 32 * j]);
            }
#pragma unroll
            for (int i = 0; i < 8; i++) {
                ulonglong2 av = *reinterpret_cast<const ulonglong2*>(
                                    &sAc[(ty * 8 + i) * 20 + kk]);
#pragma unroll
                for (int j = 0; j < 4; j++) ffma2(acc[i][j], av.x, wv0[j]);
#pragma unroll
                for (int j = 0; j < 4; j++) ffma2(acc[i][j], av.y, wv1[j]);
            }
        }

        if (pre) {
            float2* dp0 = &sA[nxt * SA_PAIRS + r0 * 20];
            dp0[kv0 + 0] = make_float2(v0.x, v0.x); dp0[kv0 + 1] = make_float2(v0.y, v0.y);
            dp0[kv0 + 2] = make_float2(v0.z, v0.z); dp0[kv0 + 3] = make_float2(v0.w, v0.w);
            float2* dp1 = &sA[nxt * SA_PAIRS + r1 * 20];
            dp1[kv1 + 0] = make_float2(v1.x, v1.x); dp1[kv1 + 1] = make_float2(v1.y, v1.y);
            dp1[kv1 + 2] = make_float2(v1.z, v1.z); dp1[kv1 + 3] = make_float2(v1.w, v1.w);
            cp_wait0();
            __syncthreads();
        }
    }

    // ---- epilogue: bias, activation, bf16 store, colsum (fp32) ----
    float2 b[4];
#pragma unroll
    for (int j = 0; j < 4; j++)
        b[j] = *reinterpret_cast<const float2*>(&bias[2 * tx + 32 * j]);

    float2 cs[4];
#pragma unroll
    for (int j = 0; j < 4; j++) cs[j] = make_float2(0.f, 0.f);

#pragma unroll
    for (int i = 0; i < 8; i++) {
        int row = row0 + ty * 8 + i;
        if (row < n) {
#pragma unroll
            for (int j = 0; j < 4; j++) {
                float2 a2 = *reinterpret_cast<float2*>(&acc[i][j]);
                float2 vv;
                vv.x = a2.x + b[j].x;
                vv.y = a2.y + b[j].y;
                if (do_leaky) {
                    vv.x = vv.x > 0.f ? vv.x : 0.01f * vv.x;
                    vv.y = vv.y > 0.f ? vv.y : 0.01f * vv.y;
                }
                cs[j].x += vv.x;
                cs[j].y += vv.y;
                if (STORE) {
                    *reinterpret_cast<__nv_bfloat162*>(
                        C + (size_t)row * HD + 2 * tx + 32 * j) =
                        __floats2bfloat162_rn(vv.x, vv.y);
                }
            }
        }
    }

    // block-level colsum reduction: sred[16][128] floats (reuse sW buffers)
    __syncthreads();
    float* sred = sW;
#pragma unroll
    for (int j = 0; j < 4; j++) {
        sred[ty * 128 + 2 * tx + 32 * j]     = cs[j].x;
        sred[ty * 128 + 2 * tx + 32 * j + 1] = cs[j].y;
    }
    __syncthreads();
    if (t < 128) {
        float s = 0.f;
#pragma unroll
        for (int r = 0; r < 16; r++) s += sred[r * 128 + t];
        atomicAdd(&colsum_slot[t], s);
    }
}

// ---------------------------------------------------------------------------
// Readout: g = (colsum/N) @ Wpred + bpred ; logits = g @ Wcls + bcls ; softmax
// ---------------------------------------------------------------------------
__global__ void final_kernel(const float* __restrict__ colsum,
                             const float* __restrict__ Wpred, const float* __restrict__ bpred,
                             const float* __restrict__ Wcls,  const float* __restrict__ bcls,
                             float* __restrict__ out, float invn)
{
    __shared__ float g[HD];
    int t = threadIdx.x;
    float acc = bpred[t];
    for (int k = 0; k < (NL + 1) * HD; k++)
        acc = fmaf(colsum[k] * invn, Wpred[k * HD + t], acc);
    g[t] = acc;
    __syncthreads();
    if (t == 0) {
        float l0 = bcls[0], l1 = bcls[1];
        for (int j = 0; j < HD; j++) {
            l0 = fmaf(g[j], Wcls[j * 2 + 0], l0);
            l1 = fmaf(g[j], Wcls[j * 2 + 1], l1);
        }
        float m  = fmaxf(l0, l1);
        float e0 = expf(l0 - m), e1 = expf(l1 - m);
        float inv = 1.0f / (e0 + e1);
        out[0] = e0 * inv;
        out[1] = e1 * inv;
    }
}

// ---------------------------------------------------------------------------
extern "C" void kernel_launch(void* const* d_in, const int* in_sizes, int n_in,
                              void* d_out, int out_size)
{
    const float* node_feat = (const float*)d_in[0];
    const float* degree    = (const float*)d_in[3];
    const float* Wn        = (const float*)d_in[4];
    const float* bn        = (const float*)d_in[5];
    const float* Wgcn      = (const float*)d_in[8];
    const float* bgcn      = (const float*)d_in[9];
    const float* Wpred     = (const float*)d_in[10];
    const float* bpred     = (const float*)d_in[11];
    const float* Wcls      = (const float*)d_in[12];
    const float* bcls      = (const float*)d_in[13];
    const int*   src       = (const int*)d_in[14];
    const int*   dst       = (const int*)d_in[15];

    const int n = in_sizes[3];
    const int e = in_sizes[14];

    float *A, *CS;
    __nv_bfloat16 *H0, *H1;
    int *CNT;
    cudaGetSymbolAddress((void**)&A,   g_bufA);
    cudaGetSymbolAddress((void**)&H0,  g_h0);
    cudaGetSymbolAddress((void**)&H1,  g_h1);
    cudaGetSymbolAddress((void**)&CS,  g_colsum);
    cudaGetSymbolAddress((void**)&CNT, g_cnt);

    static bool init_done = false;
    static cudaStream_t s2;
    static cudaEvent_t ev_fork, ev_join;
    if (!init_done) {
        cudaFuncSetAttribute(gemm_kernel<NFK, 1>, cudaFuncAttributeMaxDynamicSharedMemorySize, GEMM_SMEM);
        cudaFuncSetAttribute(gemm_kernel<HD, 1>,  cudaFuncAttributeMaxDynamicSharedMemorySize, GEMM_SMEM);
        cudaFuncSetAttribute(gemm_kernel<HD, 0>,  cudaFuncAttributeMaxDynamicSharedMemorySize, GEMM_SMEM);
        cudaStreamCreateWithFlags(&s2, cudaStreamNonBlocking);
        cudaEventCreateWithFlags(&ev_fork, cudaEventDisableTiming);
        cudaEventCreateWithFlags(&ev_join, cudaEventDisableTiming);
        init_done = true;
    }

    const int gemm_blocks   = (n + 127) / 128;
    const int edge_blocks   = (e + 255) / 256;
    const int gather_blocks = (n + 7) / 8;

    // ---- fork: CSR build on s2, overlapped with the big input GEMM ----
    cudaEventRecord(ev_fork, 0);
    cudaStreamWaitEvent(s2, ev_fork, 0);

    cudaMemsetAsync(CNT, 0, NN * sizeof(int), s2);
    hist_kernel<<<edge_blocks, 256, 0, s2>>>(dst, e);
    scan_kernel<<<1, 1024, 0, s2>>>(n);
    fill_kernel<<<edge_blocks, 256, 0, s2>>>(src, dst, degree, e);
    cudaEventRecord(ev_join, s2);

    // main stream: colsum zero + h0 = node_feat @ Wn + bn -> H0 (bf16)
    cudaMemsetAsync(CS, 0, (NL + 1) * HD * sizeof(float));
    gemm_kernel<NFK, 1><<<gemm_blocks, 256, GEMM_SMEM>>>(node_feat, Wn, bn, H0, CS, n, 0);

    // join: gathers need both the CSR and H0
    cudaStreamWaitEvent(0, ev_join, 0);

    // fusion: H1[v] = sum_{u->v} h0[u]   (bf16 -> bf16)
    gather_kernel<0><<<gather_blocks, 256>>>((const ull*)H0, H1, n);

    // layer 0: gather H1 -> A (fp32), gemm A -> H0 (bf16)
    gather_kernel<1><<<gather_blocks, 256>>>((const ull*)H1, A, n);
    gemm_kernel<HD, 1><<<gemm_blocks, 256, GEMM_SMEM>>>(A, Wgcn, bgcn, H0, CS + 1 * HD, n, 1);

    // layer 1: gather H0 -> A, gemm A -> H1
    gather_kernel<1><<<gather_blocks, 256>>>((const ull*)H0, A, n);
    gemm_kernel<HD, 1><<<gemm_blocks, 256, GEMM_SMEM>>>(A, Wgcn, bgcn, H1, CS + 2 * HD, n, 1);

    // layer 2: gather H1 -> A, gemm colsum-only (h3 never read again)
    gather_kernel<1><<<gather_blocks, 256>>>((const ull*)H1, A, n);
    gemm_kernel<HD, 0><<<gemm_blocks, 256, GEMM_SMEM>>>(A, Wgcn, bgcn, (__nv_bfloat16*)nullptr, CS + 3 * HD, n, 1);

    final_kernel<<<1, HD>>>(CS, Wpred, bpred, Wcls, bcls, (float*)d_out, 1.0f / (float)n);
}